// round 1
// baseline (speedup 1.0000x reference)
#include <cuda_runtime.h>

// MonteCarloPooling: per 2x2 block of x, Gumbel-max categorical sample using
// pre-drawn uniforms u; output = sampled index (0..3) as float.
//
// Equivalence used: argmax_k [ log(max(b_k,EPS)) - log(-log(clip(u_k))) ]
//                 = argmax_k [ max(b_k,EPS) / (-log(clip(u_k))) ]
// (exp is monotone). clip upper bound 1-1e-12 rounds to 1.0f in fp32 and
// jax.random.uniform is in [0,1), so only the lower clamp matters.

#define MCP_EPS 1e-12f

// x: (B=32, C=64, H=224, W=224) fp32
// u: (B, C, 112, 112, 4) fp32
// out: (B, C, 112, 112) fp32
static constexpr int PW   = 112;   // pooled width
static constexpr int PH   = 112;   // pooled height
static constexpr int W    = 224;   // input width

__device__ __forceinline__ float mcp_pick(float b0, float b1, float b2, float b3,
                                          float4 uu)
{
    // t_k = -log(max(u_k, EPS)) > 0
    float t0 = -logf(fmaxf(uu.x, MCP_EPS));
    float t1 = -logf(fmaxf(uu.y, MCP_EPS));
    float t2 = -logf(fmaxf(uu.z, MCP_EPS));
    float t3 = -logf(fmaxf(uu.w, MCP_EPS));

    float s0 = fmaxf(b0, MCP_EPS) / t0;
    float s1 = fmaxf(b1, MCP_EPS) / t1;
    float s2 = fmaxf(b2, MCP_EPS) / t2;
    float s3 = fmaxf(b3, MCP_EPS) / t3;

    // first-occurrence argmax (strict >)
    int   idx = 0;
    float best = s0;
    if (s1 > best) { best = s1; idx = 1; }
    if (s2 > best) { best = s2; idx = 2; }
    if (s3 > best) { best = s3; idx = 3; }
    return (float)idx;
}

__global__ void __launch_bounds__(256)
mcpool_kernel(const float* __restrict__ x,
              const float* __restrict__ u,
              float* __restrict__ out,
              int n4)  // number of 4-output groups
{
    int t = blockIdx.x * blockDim.x + threadIdx.x;
    if (t >= n4) return;

    long long o   = (long long)t * 4;      // first output element index
    int       w   = (int)(o % PW);         // pooled col (multiple of 4)
    long long row = o / PW;
    int       h   = (int)(row % PH);       // pooled row
    long long bc  = row / PH;              // fused batch*channel index

    // x block rows 2h and 2h+1, cols [2w, 2w+8)
    const float*  xbase = x + (bc * 2 * PH + 2 * h) * (long long)W + 2 * w;
    const float4* xr0   = (const float4*)xbase;         // row 2h
    const float4* xr1   = (const float4*)(xbase + W);   // row 2h+1
    float4 a0 = xr0[0];   // cols 2w..2w+3, top row
    float4 a1 = xr0[1];   // cols 2w+4..2w+7, top row
    float4 c0 = xr1[0];   // bottom row
    float4 c1 = xr1[1];

    // u: 4 contiguous floats per output, 16 per group
    const float4* up = (const float4*)(u + o * 4);
    float4 u0 = up[0];
    float4 u1 = up[1];
    float4 u2 = up[2];
    float4 u3 = up[3];

    // block flatten order k: (row_in_block, col_in_block) -> k = 2*r + c
    float4 res;
    res.x = mcp_pick(a0.x, a0.y, c0.x, c0.y, u0);
    res.y = mcp_pick(a0.z, a0.w, c0.z, c0.w, u1);
    res.z = mcp_pick(a1.x, a1.y, c1.x, c1.y, u2);
    res.w = mcp_pick(a1.z, a1.w, c1.z, c1.w, u3);

    ((float4*)out)[t] = res;
}

extern "C" void kernel_launch(void* const* d_in, const int* in_sizes, int n_in,
                              void* d_out, int out_size)
{
    const float* x = (const float*)d_in[0];
    const float* u = (const float*)d_in[1];
    float* out = (float*)d_out;

    int n4 = out_size / 4;                 // 6,422,528 groups
    int threads = 256;
    int blocks = (n4 + threads - 1) / threads;
    mcpool_kernel<<<blocks, threads>>>(x, u, out, n4);
}

// round 2
// speedup vs baseline: 1.0114x; 1.0114x over previous
#include <cuda_runtime.h>

// MonteCarloPooling: per 2x2 block of x, Gumbel-max categorical sample using
// pre-drawn uniforms u; output = sampled index (0..3) as float.
//
// Equivalence: argmax_k [ log(max(b_k,EPS)) - log(-log(clip(u_k))) ]
//            = argmax_k [ max(b_k,EPS) / (-log(clip(u_k))) ]   (exp monotone)
//
// R2: all-32-bit indexing (64-bit div/mod by 112 was ~40% ALU pipe),
//     evict-streaming loads/stores (zero reuse -> don't pollute L2).

#define MCP_EPS 1e-12f

// x: (B=32, C=64, 224, 224) fp32; u: (B,C,112,112,4) fp32; out: (B,C,112,112) fp32
static constexpr unsigned PW = 112;   // pooled width
static constexpr unsigned PH = 112;   // pooled height
static constexpr unsigned W  = 224;   // input width
static constexpr unsigned GPR = PW / 4;   // 28 float4-groups per pooled row

__device__ __forceinline__ float mcp_pick(float b0, float b1, float b2, float b3,
                                          float4 uu)
{
    // t_k = -log(max(u_k, EPS)) > 0 ; accurate logf keeps argmax-flip count tiny
    float t0 = -logf(fmaxf(uu.x, MCP_EPS));
    float t1 = -logf(fmaxf(uu.y, MCP_EPS));
    float t2 = -logf(fmaxf(uu.z, MCP_EPS));
    float t3 = -logf(fmaxf(uu.w, MCP_EPS));

    float s0 = fmaxf(b0, MCP_EPS) / t0;
    float s1 = fmaxf(b1, MCP_EPS) / t1;
    float s2 = fmaxf(b2, MCP_EPS) / t2;
    float s3 = fmaxf(b3, MCP_EPS) / t3;

    // first-occurrence argmax (strict >) == jnp.argmax semantics
    int   idx = 0;
    float best = s0;
    if (s1 > best) { best = s1; idx = 1; }
    if (s2 > best) { best = s2; idx = 2; }
    if (s3 > best) { best = s3; idx = 3; }
    return (float)idx;
}

__global__ void __launch_bounds__(256)
mcpool_kernel(const float* __restrict__ x,
              const float* __restrict__ u,
              float* __restrict__ out,
              unsigned n4)  // number of 4-output groups
{
    unsigned t = blockIdx.x * blockDim.x + threadIdx.x;
    if (t >= n4) return;

    // 32-bit decomposition: constant divisors -> magic multiplies
    unsigned g   = t % GPR;        // float4-group within pooled row (0..27)
    unsigned row = t / GPR;        // bc*PH + h
    unsigned h   = row % PH;
    unsigned bc  = row / PH;       // fused batch*channel (0..2047)

    // x block rows 2h and 2h+1, input cols [8g, 8g+8)
    const float* xbase = x + (bc * (2u * PH) + 2u * h) * W + 8u * g;
    float4 a0 = __ldcs((const float4*)xbase);           // top row, cols 8g..8g+3
    float4 a1 = __ldcs((const float4*)xbase + 1);       // top row, cols 8g+4..8g+7
    float4 c0 = __ldcs((const float4*)(xbase + W));     // bottom row
    float4 c1 = __ldcs((const float4*)(xbase + W) + 1);

    // u: 16 contiguous floats per group
    const float4* up = (const float4*)u + (t * 4u);
    float4 u0 = __ldcs(up + 0);
    float4 u1 = __ldcs(up + 1);
    float4 u2 = __ldcs(up + 2);
    float4 u3 = __ldcs(up + 3);

    // block flatten order k = 2*row_in_block + col_in_block
    float4 res;
    res.x = mcp_pick(a0.x, a0.y, c0.x, c0.y, u0);
    res.y = mcp_pick(a0.z, a0.w, c0.z, c0.w, u1);
    res.z = mcp_pick(a1.x, a1.y, c1.x, c1.y, u2);
    res.w = mcp_pick(a1.z, a1.w, c1.z, c1.w, u3);

    __stcs((float4*)out + t, res);
}

extern "C" void kernel_launch(void* const* d_in, const int* in_sizes, int n_in,
                              void* d_out, int out_size)
{
    const float* x = (const float*)d_in[0];
    const float* u = (const float*)d_in[1];
    float* out = (float*)d_out;

    unsigned n4 = (unsigned)(out_size / 4);   // 6,422,528 groups
    unsigned threads = 256;
    unsigned blocks = (n4 + threads - 1) / threads;
    mcpool_kernel<<<blocks, threads>>>(x, u, out, n4);
}